// round 9
// baseline (speedup 1.0000x reference)
#include <cuda_runtime.h>
#include <cuda_fp16.h>
#include <mma.h>
#include <cstdint>

using namespace nvcuda;

#define TSEQ 2048
#define CEMB 4096
#define QKVN 6144
#define FFNN 11008
#define NHEAD 32
#define NGRP 8
#define HSZ 128

// ------------------------- scratch (device globals) -------------------------
__device__ float g_qkv[TSEQ * QKVN];
__device__ float g_scaling[TSEQ * CEMB];
__device__ float g_scale_t[NHEAD * TSEQ];
__device__ float g_invsum[NHEAD * TSEQ];
__device__ float g_scores[134217728];            // 32 * 2048 * 2048 fp32
__device__ float g_x2[TSEQ * CEMB];
__device__ __half g_n1h[TSEQ * CEMB];
__device__ __half g_n2h[TSEQ * CEMB];
__device__ __half g_qh[NHEAD * TSEQ * HSZ];
__device__ __half g_kh[NGRP * TSEQ * HSZ];
__device__ __half g_vh[NGRP * TSEQ * HSZ];
__device__ __half g_probs[134217728];            // fp16 probs
__device__ __half g_yh[TSEQ * CEMB];
__device__ __half g_uph[TSEQ * FFNN];
__device__ __half g_acth[TSEQ * FFNN];
__device__ __half g_wqkv[QKVN * CEMB];
__device__ __half g_wscale[CEMB * CEMB];
__device__ __half g_wproj[CEMB * CEMB];
__device__ __half g_wgate[FFNN * CEMB];
__device__ __half g_wup[FFNN * CEMB];
__device__ __half g_wdown[CEMB * FFNN];

// ------------------------- cp.async helpers -------------------------
__device__ __forceinline__ void cp_async16h(__half* smem, const __half* gmem)
{
    uint32_t s = (uint32_t)__cvta_generic_to_shared(smem);
    asm volatile("cp.async.cg.shared.global [%0], [%1], 16;\n" :: "r"(s), "l"(gmem));
}
#define CP_COMMIT asm volatile("cp.async.commit_group;\n" ::: "memory")

// ===================== hgemm256: TB GEMM, 128x256x32, 3-stage ================
// C[M,N] = A[M,K] @ B[N,K]^T (+ epilogue). 256 thr, 8 warps (2x4), 64x64 tiles.
// EPI: 0=none 1=C+=epf[gm*ldc+gn] 2=C=relu(C+epf[gn]) 4=C=silu(C)*eph[gm*ldc+gn]
#define B2M 128
#define B2N 256
#define A2LD 40
#define STG2_H (128 * 40 + 256 * 40)     // 15360 halves per stage
#define GEMM2_SMEM 92160                 // 3 stages * 15360 * 2 B

template <int EPI, typename TO>
__global__ void __launch_bounds__(256, 1) hgemm256(
    const __half* __restrict__ A, const __half* __restrict__ B, TO* __restrict__ C,
    const void* __restrict__ ep,
    int M, int N, int K, int ldc,
    long long sA, long long sB, long long sC, int bDiv)
{
    extern __shared__ __align__(16) char smraw[];
    __half* smh = (__half*)smraw;

    const int z = blockIdx.z;
    A += (long long)z * sA;
    B += (long long)(z / bDiv) * sB;
    C += (long long)z * sC;

    const int m0 = blockIdx.y * B2M;
    const int n0 = blockIdx.x * B2N;
    const int tid = threadIdx.x;
    const int lane = tid & 31;
    const int warp = tid >> 5;
    const int wr = warp >> 2;   // 0..1  (64-row band)
    const int wc = warp & 3;    // 0..3  (64-col band)

    const int lr = tid >> 2;               // 0..63
    const int lc = (tid & 3) << 3;         // halves 0,8,16,24

    wmma::fragment<wmma::accumulator, 16, 16, 16, float> acc[4][4];
#pragma unroll
    for (int i = 0; i < 4; i++)
#pragma unroll
        for (int j = 0; j < 4; j++) wmma::fill_fragment(acc[i][j], 0.0f);

    const int KT = K >> 5;

    auto load_tile = [&](int kt, int st) {
        __half* As = smh + st * STG2_H;
        __half* Bs = As + 128 * 40;
        const int k0 = kt << 5;
#pragma unroll
        for (int it = 0; it < 2; it++) {
            int r = lr + it * 64;
            cp_async16h(As + r * A2LD + lc, A + (long long)(m0 + r) * K + k0 + lc);
        }
#pragma unroll
        for (int it = 0; it < 4; it++) {
            int r = lr + it * 64;
            cp_async16h(Bs + r * A2LD + lc, B + (long long)(n0 + r) * K + k0 + lc);
        }
    };

    load_tile(0, 0); CP_COMMIT;
    load_tile(1, 1); CP_COMMIT;

    for (int kt = 0; kt < KT; kt++) {
        asm volatile("cp.async.wait_group 1;\n" ::: "memory");
        __syncthreads();
        if (kt + 2 < KT) load_tile(kt + 2, (kt + 2) % 3);
        CP_COMMIT;

        __half* As = smh + (kt % 3) * STG2_H;
        __half* Bs = As + 128 * 40;
#pragma unroll
        for (int kk = 0; kk < 2; kk++) {
            wmma::fragment<wmma::matrix_a, 16, 16, 16, __half, wmma::row_major> fa[4];
#pragma unroll
            for (int i = 0; i < 4; i++)
                wmma::load_matrix_sync(fa[i], As + (wr * 64 + i * 16) * A2LD + kk * 16, A2LD);
#pragma unroll
            for (int j = 0; j < 4; j++) {
                wmma::fragment<wmma::matrix_b, 16, 16, 16, __half, wmma::col_major> fb;
                wmma::load_matrix_sync(fb, Bs + (wc * 64 + j * 16) * A2LD + kk * 16, A2LD);
#pragma unroll
                for (int i = 0; i < 4; i++)
                    wmma::mma_sync(acc[i][j], fa[i], fb, acc[i][j]);
            }
        }
    }
    __syncthreads();   // protect smem reuse for staging

    // ---- epilogue: two 32-col halves per warp, staged 64x36 fp32 ----
    float* stg = (float*)smraw + warp * (64 * 36);
    const float* epf = (const float*)ep;
    const __half* eph = (const __half*)ep;
#pragma unroll
    for (int h = 0; h < 2; h++) {
#pragma unroll
        for (int i = 0; i < 4; i++)
#pragma unroll
            for (int j = 0; j < 2; j++)
                wmma::store_matrix_sync(stg + (i * 16) * 36 + j * 16, acc[i][2 * h + j], 36,
                                        wmma::mem_row_major);
        __syncwarp();
        const int gn = n0 + wc * 64 + h * 32 + lane;
#pragma unroll 4
        for (int r = 0; r < 64; r++) {
            const int gm = m0 + wr * 64 + r;
            float v = stg[r * 36 + lane];
            if (EPI == 1) v += epf[(long long)gm * ldc + gn];
            if (EPI == 2) v = fmaxf(v + epf[gn], 0.0f);
            if (EPI == 4) v = (v / (1.f + __expf(-v))) * __half2float(eph[(long long)gm * ldc + gn]);
            if (sizeof(TO) == 2)
                ((__half*)C)[(long long)gm * ldc + gn] = __float2half(v);
            else
                ((float*)C)[(long long)gm * ldc + gn] = v;
        }
        __syncwarp();
    }
}

// ===================== hgemm (NN, 128x128, 2-stage) — AV only ================
#define BM 128
#define BN 128
#define ALD 40
#define BLDNN 136
#define STAGE_H 10240
#define GEMM_SMEM_BYTES 73728
#define SLD 36

template <int EPI, typename TO>
__global__ void __launch_bounds__(256, 2) hgemm_nn(
    const __half* __restrict__ A, const __half* __restrict__ B, TO* __restrict__ C,
    const void* __restrict__ ep,
    int M, int N, int K, int ldc,
    long long sA, long long sB, long long sC, int bDiv)
{
    extern __shared__ __align__(16) char smraw[];
    __half* smh = (__half*)smraw;

    const int z = blockIdx.z;
    A += (long long)z * sA;
    B += (long long)(z / bDiv) * sB;
    C += (long long)z * sC;

    const int m0 = blockIdx.y * BM;
    const int n0 = blockIdx.x * BN;
    const int tid = threadIdx.x;
    const int lane = tid & 31;
    const int warp = tid >> 5;
    const int wr = warp >> 2;
    const int wc = warp & 3;

    const int ar = tid >> 2, ac = (tid & 3) << 3;
    const int br = tid >> 4, bc = (tid & 15) << 3;

    wmma::fragment<wmma::accumulator, 16, 16, 16, float> acc[4][2];
#pragma unroll
    for (int i = 0; i < 4; i++)
#pragma unroll
        for (int j = 0; j < 2; j++) wmma::fill_fragment(acc[i][j], 0.0f);

    const int KT = K >> 5;

    auto load_tile = [&](int kt, int st) {
        __half* As = smh + st * STAGE_H;
        __half* Bs = As + 5120;
        const int k0 = kt << 5;
#pragma unroll
        for (int it = 0; it < 2; it++) {
            int r = ar + it * 64;
            cp_async16h(As + r * ALD + ac, A + (long long)(m0 + r) * K + k0 + ac);
        }
#pragma unroll
        for (int it = 0; it < 2; it++) {
            int r = br + it * 16;
            cp_async16h(Bs + r * BLDNN + bc, B + (long long)(k0 + r) * N + n0 + bc);
        }
    };

    load_tile(0, 0);
    CP_COMMIT;

    for (int kt = 0; kt < KT; kt++) {
        const int cur = kt & 1;
        if (kt + 1 < KT) {
            load_tile(kt + 1, cur ^ 1);
            CP_COMMIT;
            asm volatile("cp.async.wait_group 1;\n" ::: "memory");
        } else {
            asm volatile("cp.async.wait_group 0;\n" ::: "memory");
        }
        __syncthreads();

        __half* As = smh + cur * STAGE_H;
        __half* Bs = As + 5120;
#pragma unroll
        for (int kk = 0; kk < 2; kk++) {
            wmma::fragment<wmma::matrix_a, 16, 16, 16, __half, wmma::row_major> fa[4];
#pragma unroll
            for (int i = 0; i < 4; i++)
                wmma::load_matrix_sync(fa[i], As + (wr * 64 + i * 16) * ALD + kk * 16, ALD);
            wmma::fragment<wmma::matrix_b, 16, 16, 16, __half, wmma::row_major> fb[2];
#pragma unroll
            for (int j = 0; j < 2; j++)
                wmma::load_matrix_sync(fb[j], Bs + (kk * 16) * BLDNN + wc * 32 + j * 16, BLDNN);
#pragma unroll
            for (int i = 0; i < 4; i++)
#pragma unroll
                for (int j = 0; j < 2; j++)
                    wmma::mma_sync(acc[i][j], fa[i], fb[j], acc[i][j]);
        }
        __syncthreads();
    }

    float* stg = (float*)smraw + warp * (64 * SLD);
#pragma unroll
    for (int i = 0; i < 4; i++)
#pragma unroll
        for (int j = 0; j < 2; j++)
            wmma::store_matrix_sync(stg + (i * 16) * SLD + j * 16, acc[i][j], SLD,
                                    wmma::mem_row_major);
    __syncwarp();

    const float* epf = (const float*)ep;
    const int gn = n0 + wc * 32 + lane;
#pragma unroll 4
    for (int r = 0; r < 64; r++) {
        const int gm = m0 + wr * 64 + r;
        float v = stg[r * SLD + lane];
        if (EPI == 3) v *= epf[(long long)z * M + gm];
        if (sizeof(TO) == 2)
            ((__half*)C)[(long long)gm * ldc + gn] = __float2half(v);
        else
            ((float*)C)[(long long)gm * ldc + gn] = v;
    }
}

// ------------------------- small kernels -------------------------

__global__ void w2h_kernel(const float* __restrict__ in, __half* __restrict__ out)
{
    const long long i = ((long long)blockIdx.x * 256 + threadIdx.x) * 4;
    float4 v = *(const float4*)(in + i);
    __half2* o = (__half2*)(out + i);
    o[0] = __floats2half2_rn(v.x, v.y);
    o[1] = __floats2half2_rn(v.z, v.w);
}

__global__ void rmsnorm_kernel(const float* __restrict__ x, const float* __restrict__ w,
                               __half* __restrict__ out)
{
    __shared__ float red[256];
    const int t = blockIdx.x;
    const float* row = x + (size_t)t * CEMB;
    __half* orow = out + (size_t)t * CEMB;
    const int tid = threadIdx.x;
    float s = 0.f;
    for (int i = tid; i < CEMB; i += 256) { float v = row[i]; s += v * v; }
    red[tid] = s;
    __syncthreads();
    for (int st = 128; st > 0; st >>= 1) {
        if (tid < st) red[tid] += red[tid + st];
        __syncthreads();
    }
    const float inv = rsqrtf(red[0] * (1.0f / CEMB) + 1e-5f);
    for (int i = tid; i < CEMB; i += 256) orow[i] = __float2half(row[i] * inv * w[i]);
}

__global__ void scale_reduce_kernel(const float* __restrict__ s, float* __restrict__ st)
{
    const int pair = blockIdx.x * 8 + (threadIdx.x >> 5);
    const int lane = threadIdx.x & 31;
    const int t = pair >> 5;
    const int h = pair & 31;
    const float* p = s + (size_t)t * CEMB + h * HSZ;
    float acc = 0.f;
    for (int d = lane; d < HSZ; d += 32) acc += p[d];
    for (int o = 16; o; o >>= 1) acc += __shfl_down_sync(0xffffffffu, acc, o);
    if (lane == 0) st[h * TSEQ + t] = acc * (1.0f / HSZ);
}

__global__ void qkv_rope_kernel(const float* __restrict__ qkv, const float* __restrict__ cs,
                                const float* __restrict__ sn, const float* __restrict__ st,
                                __half* __restrict__ q, __half* __restrict__ k,
                                __half* __restrict__ v)
{
    const int idx = blockIdx.x * 256 + threadIdx.x;
    const int d = idx & 127;
    const int rest = idx >> 7;
    const int slot = rest % 48;
    const int t = rest / 48;
    const int g = slot / 6;
    const int i = slot % 6;
    const float* src = qkv + (size_t)t * QKVN + g * 768 + i * 128;
    const float x0 = src[d];
    if (i == 5) {
        v[((size_t)g * TSEQ + t) * HSZ + d] = __float2half(x0);
        return;
    }
    const float xp = src[d ^ 64];
    const float rot = (d < 64) ? -xp : xp;
    const float val = x0 * cs[t * 128 + d] + rot * sn[t * 128 + d];
    if (i == 4) {
        k[((size_t)g * TSEQ + t) * HSZ + d] = __float2half(val);
    } else {
        const int h = g * 4 + i;
        q[((size_t)h * TSEQ + t) * HSZ + d] =
            __float2half(val * (0.08838834764831845f * st[h * TSEQ + t]));
    }
}

__global__ void softmax_kernel(const float* __restrict__ scores, __half* __restrict__ probs,
                               float* __restrict__ invsum)
{
    __shared__ float red[256];
    const size_t row = blockIdx.x;
    const float* p = scores + row * TSEQ;
    __half* ph = probs + row * TSEQ;
    const int tid = threadIdx.x;

    float m = -1e30f;
    for (int i = tid; i < TSEQ; i += 256) m = fmaxf(m, p[i]);
    red[tid] = m;
    __syncthreads();
    for (int st = 128; st > 0; st >>= 1) {
        if (tid < st) red[tid] = fmaxf(red[tid], red[tid + st]);
        __syncthreads();
    }
    m = red[0];
    __syncthreads();

    float sum = 0.f;
    for (int i = tid; i < TSEQ; i += 256) {
        float e = __expf(p[i] - m);
        ph[i] = __float2half(e);
        sum += e;
    }
    red[tid] = sum;
    __syncthreads();
    for (int st = 128; st > 0; st >>= 1) {
        if (tid < st) red[tid] += red[tid + st];
        __syncthreads();
    }
    if (tid == 0) invsum[row] = 1.f / red[0];
}

// ------------------------- host side -------------------------

template <int EPI, typename TO>
static inline void run_g256(const __half* A, const __half* B, TO* C, const void* ep,
                            int M, int N, int K, int ldc,
                            long long sA = 0, long long sB = 0, long long sC = 0,
                            int bDiv = 1, int nb = 1)
{
    cudaFuncSetAttribute(hgemm256<EPI, TO>,
                         cudaFuncAttributeMaxDynamicSharedMemorySize, GEMM2_SMEM);
    dim3 grid(N / B2N, M / B2M, nb);
    hgemm256<EPI, TO><<<grid, 256, GEMM2_SMEM>>>(A, B, C, ep, M, N, K, ldc, sA, sB, sC, bDiv);
}

template <int EPI, typename TO>
static inline void run_nn(const __half* A, const __half* B, TO* C, const void* ep,
                          int M, int N, int K, int ldc,
                          long long sA, long long sB, long long sC, int bDiv, int nb)
{
    cudaFuncSetAttribute(hgemm_nn<EPI, TO>,
                         cudaFuncAttributeMaxDynamicSharedMemorySize, GEMM_SMEM_BYTES);
    dim3 grid(N / BN, M / BM, nb);
    hgemm_nn<EPI, TO><<<grid, 256, GEMM_SMEM_BYTES>>>(A, B, C, ep, M, N, K, ldc, sA, sB, sC, bDiv);
}

static inline void conv_w(const float* in, __half* out, long long n)
{
    w2h_kernel<<<(unsigned)(n / 1024), 256>>>(in, out);
}

extern "C" void kernel_launch(void* const* d_in, const int* in_sizes, int n_in,
                              void* d_out, int out_size)
{
    (void)in_sizes; (void)n_in; (void)out_size;
    const float* x       = (const float*)d_in[0];
    const float* cosp    = (const float*)d_in[1];
    const float* sinp    = (const float*)d_in[2];
    const float* n1w     = (const float*)d_in[3];
    const float* n2w     = (const float*)d_in[4];
    const float* attn_w  = (const float*)d_in[5];
    const float* proj_w  = (const float*)d_in[6];
    const float* scale_w = (const float*)d_in[7];
    const float* scale_b = (const float*)d_in[8];
    const float* gate_w  = (const float*)d_in[9];
    const float* up_w    = (const float*)d_in[10];
    const float* down_w  = (const float*)d_in[11];
    float* out = (float*)d_out;

    float *p_qkv, *p_scaling, *p_st, *p_is, *p_sc, *p_x2;
    __half *p_n1h, *p_n2h, *p_qh, *p_kh, *p_vh, *p_probs, *p_yh, *p_uph, *p_acth;
    __half *p_wqkv, *p_wscale, *p_wproj, *p_wgate, *p_wup, *p_wdown;
    cudaGetSymbolAddress((void**)&p_qkv, g_qkv);
    cudaGetSymbolAddress((void**)&p_scaling, g_scaling);
    cudaGetSymbolAddress((void**)&p_st, g_scale_t);
    cudaGetSymbolAddress((void**)&p_is, g_invsum);
    cudaGetSymbolAddress((void**)&p_sc, g_scores);
    cudaGetSymbolAddress((void**)&p_x2, g_x2);
    cudaGetSymbolAddress((void**)&p_n1h, g_n1h);
    cudaGetSymbolAddress((void**)&p_n2h, g_n2h);
    cudaGetSymbolAddress((void**)&p_qh, g_qh);
    cudaGetSymbolAddress((void**)&p_kh, g_kh);
    cudaGetSymbolAddress((void**)&p_vh, g_vh);
    cudaGetSymbolAddress((void**)&p_probs, g_probs);
    cudaGetSymbolAddress((void**)&p_yh, g_yh);
    cudaGetSymbolAddress((void**)&p_uph, g_uph);
    cudaGetSymbolAddress((void**)&p_acth, g_acth);
    cudaGetSymbolAddress((void**)&p_wqkv, g_wqkv);
    cudaGetSymbolAddress((void**)&p_wscale, g_wscale);
    cudaGetSymbolAddress((void**)&p_wproj, g_wproj);
    cudaGetSymbolAddress((void**)&p_wgate, g_wgate);
    cudaGetSymbolAddress((void**)&p_wup, g_wup);
    cudaGetSymbolAddress((void**)&p_wdown, g_wdown);

    // 0. weights -> fp16
    conv_w(attn_w,  p_wqkv,   (long long)QKVN * CEMB);
    conv_w(scale_w, p_wscale, (long long)CEMB * CEMB);
    conv_w(proj_w,  p_wproj,  (long long)CEMB * CEMB);
    conv_w(gate_w,  p_wgate,  (long long)FFNN * CEMB);
    conv_w(up_w,    p_wup,    (long long)FFNN * CEMB);
    conv_w(down_w,  p_wdown,  (long long)CEMB * FFNN);

    // 1. n1 = rmsnorm(x)
    rmsnorm_kernel<<<TSEQ, 256>>>(x, n1w, p_n1h);
    // 2. qkv = n1 @ attn_w^T
    run_g256<0, float>(p_n1h, p_wqkv, p_qkv, nullptr, TSEQ, QKVN, CEMB, QKVN);
    // 3. scaling = relu(n1 @ scale_w^T + b)
    run_g256<2, float>(p_n1h, p_wscale, p_scaling, scale_b, TSEQ, CEMB, CEMB, CEMB);
    // 4. scale_t
    scale_reduce_kernel<<<TSEQ * NHEAD / 8, 256>>>(p_scaling, p_st);
    // 5. split + rope (fold sf*scale_t into q)
    qkv_rope_kernel<<<TSEQ * 48 * HSZ / 256, 256>>>(p_qkv, cosp, sinp, p_st, p_qh, p_kh, p_vh);
    // 6. scores[h] = q[h] @ k[h/4]^T
    run_g256<0, float>(p_qh, p_kh, p_sc, nullptr, TSEQ, TSEQ, HSZ, TSEQ,
                       (long long)TSEQ * HSZ, (long long)TSEQ * HSZ,
                       (long long)TSEQ * TSEQ, 4, NHEAD);
    // 7. softmax
    softmax_kernel<<<NHEAD * TSEQ, 256>>>(p_sc, p_probs, p_is);
    // 8. y[h] = probs[h] @ v[h/4] * invsum
    run_nn<3, __half>(p_probs, p_vh, p_yh, p_is, TSEQ, HSZ, TSEQ, CEMB,
                      (long long)TSEQ * TSEQ, (long long)TSEQ * HSZ, HSZ, 4, NHEAD);
    // 9. x2 = y @ proj_w^T + x
    run_g256<1, float>(p_yh, p_wproj, p_x2, x, TSEQ, CEMB, CEMB, CEMB);
    // 10. n2 = rmsnorm(x2)
    rmsnorm_kernel<<<TSEQ, 256>>>(p_x2, n2w, p_n2h);
    // 11. up, then gate with fused silu(gate)*up
    run_g256<0, __half>(p_n2h, p_wup, p_uph, nullptr, TSEQ, FFNN, CEMB, FFNN);
    run_g256<4, __half>(p_n2h, p_wgate, p_acth, p_uph, TSEQ, FFNN, CEMB, FFNN);
    // 12. out = act @ down_w^T + x2
    run_g256<1, float>(p_acth, p_wdown, out, p_x2, TSEQ, CEMB, FFNN, CEMB);
}

// round 13
// speedup vs baseline: 1.1745x; 1.1745x over previous
#include <cuda_runtime.h>
#include <cuda_fp16.h>
#include <mma.h>
#include <cstdint>

using namespace nvcuda;

#define TSEQ 2048
#define CEMB 4096
#define QKVN 6144
#define FFNN 11008
#define NHEAD 32
#define NGRP 8
#define HSZ 128

// ------------------------- scratch (device globals) -------------------------
__device__ float g_qkv[TSEQ * QKVN];
__device__ float g_scaling[TSEQ * CEMB];
__device__ float g_scale_t[NHEAD * TSEQ];
__device__ float g_invsum[NHEAD * TSEQ];
__device__ float g_scores[134217728];            // 32 * 2048 * 2048 fp32
__device__ float g_x2[TSEQ * CEMB];
__device__ __half g_n1h[TSEQ * CEMB];
__device__ __half g_n2h[TSEQ * CEMB];
__device__ __half g_qh[NHEAD * TSEQ * HSZ];
__device__ __half g_kh[NGRP * TSEQ * HSZ];
__device__ __half g_vh[NGRP * TSEQ * HSZ];
__device__ __half g_probs[134217728];            // fp16 probs
__device__ __half g_yh[TSEQ * CEMB];
__device__ __half g_uph[TSEQ * FFNN];
__device__ __half g_acth[TSEQ * FFNN];
__device__ __half g_wqkv[QKVN * CEMB];
__device__ __half g_wscale[CEMB * CEMB];
__device__ __half g_wproj[CEMB * CEMB];
__device__ __half g_wgate[FFNN * CEMB];
__device__ __half g_wup[FFNN * CEMB];
__device__ __half g_wdown[CEMB * FFNN];

// ------------------------- cp.async helpers -------------------------
__device__ __forceinline__ void cp_async16h(__half* smem, const __half* gmem)
{
    uint32_t s = (uint32_t)__cvta_generic_to_shared(smem);
    asm volatile("cp.async.cg.shared.global [%0], [%1], 16;\n" :: "r"(s), "l"(gmem));
}
#define CP_COMMIT asm volatile("cp.async.commit_group;\n" ::: "memory")

// ===================== wgemm: weight GEMMs, 128x128x32, 4 warps, 3-stage =====
// C[M,N] = A[M,K] @ B[N,K]^T (+epilogue). 128 thr, 4 warps (2x2), 64x64 tiles,
// 3-stage cp.async, 2 CTAs/SM.
// EPI: 0=none 1=C+=epf[gm*ldc+gn] 2=C=relu(C+epf[gn]) 4=C=silu(C)*eph[gm*ldc+gn]
#define WLD 40
#define WSTG_H 10240                 // halves per stage (A 128x40 + B 128x40)
#define WSMEM 61440                  // 3 stages * 10240 * 2 B

template <int EPI, typename TO>
__global__ void __launch_bounds__(128, 2) wgemm(
    const __half* __restrict__ A, const __half* __restrict__ B, TO* __restrict__ C,
    const void* __restrict__ ep, int M, int N, int K, int ldc)
{
    extern __shared__ __align__(16) char smraw[];
    __half* smh = (__half*)smraw;

    const int m0 = blockIdx.y * 128;
    const int n0 = blockIdx.x * 128;
    const int tid = threadIdx.x;
    const int lane = tid & 31;
    const int warp = tid >> 5;
    const int wr = warp >> 1;   // 0..1 (64-row band)
    const int wc = warp & 1;    // 0..1 (64-col band)

    const int lr = tid >> 2;             // 0..31
    const int lc = (tid & 3) << 3;       // halves 0,8,16,24

    wmma::fragment<wmma::accumulator, 16, 16, 16, float> acc[4][4];
#pragma unroll
    for (int i = 0; i < 4; i++)
#pragma unroll
        for (int j = 0; j < 4; j++) wmma::fill_fragment(acc[i][j], 0.0f);

    const int KT = K >> 5;

    auto load_tile = [&](int kt, int st) {
        __half* As = smh + st * WSTG_H;
        __half* Bs = As + 128 * WLD;
        const int k0 = kt << 5;
#pragma unroll
        for (int it = 0; it < 4; it++) {
            int r = lr + it * 32;
            cp_async16h(As + r * WLD + lc, A + (long long)(m0 + r) * K + k0 + lc);
            cp_async16h(Bs + r * WLD + lc, B + (long long)(n0 + r) * K + k0 + lc);
        }
    };

    load_tile(0, 0); CP_COMMIT;
    load_tile(1, 1); CP_COMMIT;

    for (int kt = 0; kt < KT; kt++) {
        asm volatile("cp.async.wait_group 1;\n" ::: "memory");
        __syncthreads();
        if (kt + 2 < KT) load_tile(kt + 2, (kt + 2) % 3);
        CP_COMMIT;

        __half* As = smh + (kt % 3) * WSTG_H;
        __half* Bs = As + 128 * WLD;
#pragma unroll
        for (int kk = 0; kk < 2; kk++) {
            wmma::fragment<wmma::matrix_a, 16, 16, 16, __half, wmma::row_major> fa[4];
#pragma unroll
            for (int i = 0; i < 4; i++)
                wmma::load_matrix_sync(fa[i], As + (wr * 64 + i * 16) * WLD + kk * 16, WLD);
#pragma unroll
            for (int j = 0; j < 4; j++) {
                wmma::fragment<wmma::matrix_b, 16, 16, 16, __half, wmma::col_major> fb;
                wmma::load_matrix_sync(fb, Bs + (wc * 64 + j * 16) * WLD + kk * 16, WLD);
#pragma unroll
                for (int i = 0; i < 4; i++)
                    wmma::mma_sync(acc[i][j], fa[i], fb, acc[i][j]);
            }
        }
    }
    __syncthreads();   // protect smem reuse for staging

    // ---- epilogue: two 32-col halves per warp, staged 64x36 fp32 ----
    float* stg = (float*)smraw + warp * (64 * 36);
    const float* epf = (const float*)ep;
    const __half* eph = (const __half*)ep;
#pragma unroll
    for (int h = 0; h < 2; h++) {
#pragma unroll
        for (int i = 0; i < 4; i++)
#pragma unroll
            for (int j = 0; j < 2; j++)
                wmma::store_matrix_sync(stg + (i * 16) * 36 + j * 16, acc[i][2 * h + j], 36,
                                        wmma::mem_row_major);
        __syncwarp();
        const int gn = n0 + wc * 64 + h * 32 + lane;
#pragma unroll 4
        for (int r = 0; r < 64; r++) {
            const int gm = m0 + wr * 64 + r;
            float v = stg[r * 36 + lane];
            if (EPI == 1) v += epf[(long long)gm * ldc + gn];
            if (EPI == 2) v = fmaxf(v + epf[gn], 0.0f);
            if (EPI == 4) v = (v / (1.f + __expf(-v))) * __half2float(eph[(long long)gm * ldc + gn]);
            if (sizeof(TO) == 2)
                ((__half*)C)[(long long)gm * ldc + gn] = __float2half(v);
            else
                ((float*)C)[(long long)gm * ldc + gn] = v;
        }
        __syncwarp();
    }
}

// ===================== hgemm: R7 kernel (attention GEMMs) ====================
#define BM 128
#define BN 128
#define ALD 40
#define BLDNN 136
#define STAGE_H 10240
#define GEMM_SMEM_BYTES 73728
#define SLD 36

template <bool TB, int EPI, typename TO>
__global__ void __launch_bounds__(256, 2) hgemm(
    const __half* __restrict__ A, const __half* __restrict__ B, TO* __restrict__ C,
    const void* __restrict__ ep,
    int M, int N, int K, int ldc,
    long long sA, long long sB, long long sC, int bDiv)
{
    extern __shared__ __align__(16) char smraw[];
    __half* smh = (__half*)smraw;

    const int z = blockIdx.z;
    A += (long long)z * sA;
    B += (long long)(z / bDiv) * sB;
    C += (long long)z * sC;

    const int m0 = blockIdx.y * BM;
    const int n0 = blockIdx.x * BN;
    const int tid = threadIdx.x;
    const int lane = tid & 31;
    const int warp = tid >> 5;
    const int wr = warp >> 2;
    const int wc = warp & 3;

    const int ar = tid >> 2, ac = (tid & 3) << 3;
    const int br = tid >> 4, bc = (tid & 15) << 3;

    wmma::fragment<wmma::accumulator, 16, 16, 16, float> acc[4][2];
#pragma unroll
    for (int i = 0; i < 4; i++)
#pragma unroll
        for (int j = 0; j < 2; j++) wmma::fill_fragment(acc[i][j], 0.0f);

    const int KT = K >> 5;

    auto load_tile = [&](int kt, int st) {
        __half* As = smh + st * STAGE_H;
        __half* Bs = As + 5120;
        const int k0 = kt << 5;
#pragma unroll
        for (int it = 0; it < 2; it++) {
            int r = ar + it * 64;
            cp_async16h(As + r * ALD + ac, A + (long long)(m0 + r) * K + k0 + ac);
        }
        if (TB) {
#pragma unroll
            for (int it = 0; it < 2; it++) {
                int r = ar + it * 64;
                cp_async16h(Bs + r * ALD + ac, B + (long long)(n0 + r) * K + k0 + ac);
            }
        } else {
#pragma unroll
            for (int it = 0; it < 2; it++) {
                int r = br + it * 16;
                cp_async16h(Bs + r * BLDNN + bc, B + (long long)(k0 + r) * N + n0 + bc);
            }
        }
    };

    load_tile(0, 0);
    CP_COMMIT;

    for (int kt = 0; kt < KT; kt++) {
        const int cur = kt & 1;
        if (kt + 1 < KT) {
            load_tile(kt + 1, cur ^ 1);
            CP_COMMIT;
            asm volatile("cp.async.wait_group 1;\n" ::: "memory");
        } else {
            asm volatile("cp.async.wait_group 0;\n" ::: "memory");
        }
        __syncthreads();

        __half* As = smh + cur * STAGE_H;
        __half* Bs = As + 5120;
#pragma unroll
        for (int kk = 0; kk < 2; kk++) {
            wmma::fragment<wmma::matrix_a, 16, 16, 16, __half, wmma::row_major> fa[4];
#pragma unroll
            for (int i = 0; i < 4; i++)
                wmma::load_matrix_sync(fa[i], As + (wr * 64 + i * 16) * ALD + kk * 16, ALD);
            if (TB) {
                wmma::fragment<wmma::matrix_b, 16, 16, 16, __half, wmma::col_major> fb[2];
#pragma unroll
                for (int j = 0; j < 2; j++)
                    wmma::load_matrix_sync(fb[j], Bs + (wc * 32 + j * 16) * ALD + kk * 16, ALD);
#pragma unroll
                for (int i = 0; i < 4; i++)
#pragma unroll
                    for (int j = 0; j < 2; j++)
                        wmma::mma_sync(acc[i][j], fa[i], fb[j], acc[i][j]);
            } else {
                wmma::fragment<wmma::matrix_b, 16, 16, 16, __half, wmma::row_major> fb[2];
#pragma unroll
                for (int j = 0; j < 2; j++)
                    wmma::load_matrix_sync(fb[j], Bs + (kk * 16) * BLDNN + wc * 32 + j * 16, BLDNN);
#pragma unroll
                for (int i = 0; i < 4; i++)
#pragma unroll
                    for (int j = 0; j < 2; j++)
                        wmma::mma_sync(acc[i][j], fa[i], fb[j], acc[i][j]);
            }
        }
        __syncthreads();
    }

    float* stg = (float*)smraw + warp * (64 * SLD);
#pragma unroll
    for (int i = 0; i < 4; i++)
#pragma unroll
        for (int j = 0; j < 2; j++)
            wmma::store_matrix_sync(stg + (i * 16) * SLD + j * 16, acc[i][j], SLD,
                                    wmma::mem_row_major);
    __syncwarp();

    const float* epf = (const float*)ep;
    const int gn = n0 + wc * 32 + lane;
#pragma unroll 4
    for (int r = 0; r < 64; r++) {
        const int gm = m0 + wr * 64 + r;
        float v = stg[r * SLD + lane];
        if (EPI == 3) v *= epf[(long long)z * M + gm];
        if (sizeof(TO) == 2)
            ((__half*)C)[(long long)gm * ldc + gn] = __float2half(v);
        else
            ((float*)C)[(long long)gm * ldc + gn] = v;
    }
}

// ------------------------- small kernels -------------------------

__global__ void w2h_kernel(const float* __restrict__ in, __half* __restrict__ out)
{
    const long long i = ((long long)blockIdx.x * 256 + threadIdx.x) * 4;
    float4 v = *(const float4*)(in + i);
    __half2* o = (__half2*)(out + i);
    o[0] = __floats2half2_rn(v.x, v.y);
    o[1] = __floats2half2_rn(v.z, v.w);
}

__global__ void rmsnorm_kernel(const float* __restrict__ x, const float* __restrict__ w,
                               __half* __restrict__ out)
{
    __shared__ float red[256];
    const int t = blockIdx.x;
    const float* row = x + (size_t)t * CEMB;
    __half* orow = out + (size_t)t * CEMB;
    const int tid = threadIdx.x;
    float s = 0.f;
    for (int i = tid; i < CEMB; i += 256) { float v = row[i]; s += v * v; }
    red[tid] = s;
    __syncthreads();
    for (int st = 128; st > 0; st >>= 1) {
        if (tid < st) red[tid] += red[tid + st];
        __syncthreads();
    }
    const float inv = rsqrtf(red[0] * (1.0f / CEMB) + 1e-5f);
    for (int i = tid; i < CEMB; i += 256) orow[i] = __float2half(row[i] * inv * w[i]);
}

__global__ void scale_reduce_kernel(const float* __restrict__ s, float* __restrict__ st)
{
    const int pair = blockIdx.x * 8 + (threadIdx.x >> 5);
    const int lane = threadIdx.x & 31;
    const int t = pair >> 5;
    const int h = pair & 31;
    const float* p = s + (size_t)t * CEMB + h * HSZ;
    float acc = 0.f;
    for (int d = lane; d < HSZ; d += 32) acc += p[d];
    for (int o = 16; o; o >>= 1) acc += __shfl_down_sync(0xffffffffu, acc, o);
    if (lane == 0) st[h * TSEQ + t] = acc * (1.0f / HSZ);
}

__global__ void qkv_rope_kernel(const float* __restrict__ qkv, const float* __restrict__ cs,
                                const float* __restrict__ sn, const float* __restrict__ st,
                                __half* __restrict__ q, __half* __restrict__ k,
                                __half* __restrict__ v)
{
    const int idx = blockIdx.x * 256 + threadIdx.x;
    const int d = idx & 127;
    const int rest = idx >> 7;
    const int slot = rest % 48;
    const int t = rest / 48;
    const int g = slot / 6;
    const int i = slot % 6;
    const float* src = qkv + (size_t)t * QKVN + g * 768 + i * 128;
    const float x0 = src[d];
    if (i == 5) {
        v[((size_t)g * TSEQ + t) * HSZ + d] = __float2half(x0);
        return;
    }
    const float xp = src[d ^ 64];
    const float rot = (d < 64) ? -xp : xp;
    const float val = x0 * cs[t * 128 + d] + rot * sn[t * 128 + d];
    if (i == 4) {
        k[((size_t)g * TSEQ + t) * HSZ + d] = __float2half(val);
    } else {
        const int h = g * 4 + i;
        q[((size_t)h * TSEQ + t) * HSZ + d] =
            __float2half(val * (0.08838834764831845f * st[h * TSEQ + t]));
    }
}

__global__ void softmax_kernel(const float* __restrict__ scores, __half* __restrict__ probs,
                               float* __restrict__ invsum)
{
    __shared__ float red[256];
    const size_t row = blockIdx.x;
    const float* p = scores + row * TSEQ;
    __half* ph = probs + row * TSEQ;
    const int tid = threadIdx.x;

    float m = -1e30f;
    for (int i = tid; i < TSEQ; i += 256) m = fmaxf(m, p[i]);
    red[tid] = m;
    __syncthreads();
    for (int st = 128; st > 0; st >>= 1) {
        if (tid < st) red[tid] = fmaxf(red[tid], red[tid + st]);
        __syncthreads();
    }
    m = red[0];
    __syncthreads();

    float sum = 0.f;
    for (int i = tid; i < TSEQ; i += 256) {
        float e = __expf(p[i] - m);
        ph[i] = __float2half(e);
        sum += e;
    }
    red[tid] = sum;
    __syncthreads();
    for (int st = 128; st > 0; st >>= 1) {
        if (tid < st) red[tid] += red[tid + st];
        __syncthreads();
    }
    if (tid == 0) invsum[row] = 1.f / red[0];
}

// ------------------------- host side -------------------------

template <int EPI, typename TO>
static inline void run_w(const __half* A, const __half* B, TO* C, const void* ep,
                         int M, int N, int K, int ldc)
{
    cudaFuncSetAttribute(wgemm<EPI, TO>,
                         cudaFuncAttributeMaxDynamicSharedMemorySize, WSMEM);
    dim3 grid(N / 128, M / 128);
    wgemm<EPI, TO><<<grid, 128, WSMEM>>>(A, B, C, ep, M, N, K, ldc);
}

template <bool TB, int EPI, typename TO>
static inline void run_h(const __half* A, const __half* B, TO* C, const void* ep,
                         int M, int N, int K, int ldc,
                         long long sA, long long sB, long long sC, int bDiv, int nb)
{
    cudaFuncSetAttribute(hgemm<TB, EPI, TO>,
                         cudaFuncAttributeMaxDynamicSharedMemorySize, GEMM_SMEM_BYTES);
    dim3 grid(N / BN, M / BM, nb);
    hgemm<TB, EPI, TO><<<grid, 256, GEMM_SMEM_BYTES>>>(A, B, C, ep, M, N, K, ldc,
                                                       sA, sB, sC, bDiv);
}

static inline void conv_w(const float* in, __half* out, long long n)
{
    w2h_kernel<<<(unsigned)(n / 1024), 256>>>(in, out);
}

extern "C" void kernel_launch(void* const* d_in, const int* in_sizes, int n_in,
                              void* d_out, int out_size)
{
    (void)in_sizes; (void)n_in; (void)out_size;
    const float* x       = (const float*)d_in[0];
    const float* cosp    = (const float*)d_in[1];
    const float* sinp    = (const float*)d_in[2];
    const float* n1w     = (const float*)d_in[3];
    const float* n2w     = (const float*)d_in[4];
    const float* attn_w  = (const float*)d_in[5];
    const float* proj_w  = (const float*)d_in[6];
    const float* scale_w = (const float*)d_in[7];
    const float* scale_b = (const float*)d_in[8];
    const float* gate_w  = (const float*)d_in[9];
    const float* up_w    = (const float*)d_in[10];
    const float* down_w  = (const float*)d_in[11];
    float* out = (float*)d_out;

    float *p_qkv, *p_scaling, *p_st, *p_is, *p_sc, *p_x2;
    __half *p_n1h, *p_n2h, *p_qh, *p_kh, *p_vh, *p_probs, *p_yh, *p_uph, *p_acth;
    __half *p_wqkv, *p_wscale, *p_wproj, *p_wgate, *p_wup, *p_wdown;
    cudaGetSymbolAddress((void**)&p_qkv, g_qkv);
    cudaGetSymbolAddress((void**)&p_scaling, g_scaling);
    cudaGetSymbolAddress((void**)&p_st, g_scale_t);
    cudaGetSymbolAddress((void**)&p_is, g_invsum);
    cudaGetSymbolAddress((void**)&p_sc, g_scores);
    cudaGetSymbolAddress((void**)&p_x2, g_x2);
    cudaGetSymbolAddress((void**)&p_n1h, g_n1h);
    cudaGetSymbolAddress((void**)&p_n2h, g_n2h);
    cudaGetSymbolAddress((void**)&p_qh, g_qh);
    cudaGetSymbolAddress((void**)&p_kh, g_kh);
    cudaGetSymbolAddress((void**)&p_vh, g_vh);
    cudaGetSymbolAddress((void**)&p_probs, g_probs);
    cudaGetSymbolAddress((void**)&p_yh, g_yh);
    cudaGetSymbolAddress((void**)&p_uph, g_uph);
    cudaGetSymbolAddress((void**)&p_acth, g_acth);
    cudaGetSymbolAddress((void**)&p_wqkv, g_wqkv);
    cudaGetSymbolAddress((void**)&p_wscale, g_wscale);
    cudaGetSymbolAddress((void**)&p_wproj, g_wproj);
    cudaGetSymbolAddress((void**)&p_wgate, g_wgate);
    cudaGetSymbolAddress((void**)&p_wup, g_wup);
    cudaGetSymbolAddress((void**)&p_wdown, g_wdown);

    // 0. weights -> fp16
    conv_w(attn_w,  p_wqkv,   (long long)QKVN * CEMB);
    conv_w(scale_w, p_wscale, (long long)CEMB * CEMB);
    conv_w(proj_w,  p_wproj,  (long long)CEMB * CEMB);
    conv_w(gate_w,  p_wgate,  (long long)FFNN * CEMB);
    conv_w(up_w,    p_wup,    (long long)FFNN * CEMB);
    conv_w(down_w,  p_wdown,  (long long)CEMB * FFNN);

    // 1. n1 = rmsnorm(x)
    rmsnorm_kernel<<<TSEQ, 256>>>(x, n1w, p_n1h);
    // 2. qkv = n1 @ attn_w^T
    run_w<0, float>(p_n1h, p_wqkv, p_qkv, nullptr, TSEQ, QKVN, CEMB, QKVN);
    // 3. scaling = relu(n1 @ scale_w^T + b)
    run_w<2, float>(p_n1h, p_wscale, p_scaling, scale_b, TSEQ, CEMB, CEMB, CEMB);
    // 4. scale_t
    scale_reduce_kernel<<<TSEQ * NHEAD / 8, 256>>>(p_scaling, p_st);
    // 5. split + rope (fold sf*scale_t into q)
    qkv_rope_kernel<<<TSEQ * 48 * HSZ / 256, 256>>>(p_qkv, cosp, sinp, p_st, p_qh, p_kh, p_vh);
    // 6. scores[h] = q[h] @ k[h/4]^T
    run_h<true, 0, float>(p_qh, p_kh, p_sc, nullptr, TSEQ, TSEQ, HSZ, TSEQ,
                          (long long)TSEQ * HSZ, (long long)TSEQ * HSZ,
                          (long long)TSEQ * TSEQ, 4, NHEAD);
    // 7. softmax
    softmax_kernel<<<NHEAD * TSEQ, 256>>>(p_sc, p_probs, p_is);
    // 8. y[h] = probs[h] @ v[h/4] * invsum
    run_h<false, 3, __half>(p_probs, p_vh, p_yh, p_is, TSEQ, HSZ, TSEQ, CEMB,
                            (long long)TSEQ * TSEQ, (long long)TSEQ * HSZ, HSZ, 4, NHEAD);
    // 9. x2 = y @ proj_w^T + x
    run_w<1, float>(p_yh, p_wproj, p_x2, x, TSEQ, CEMB, CEMB, CEMB);
    // 10. n2 = rmsnorm(x2)
    rmsnorm_kernel<<<TSEQ, 256>>>(p_x2, n2w, p_n2h);
    // 11. up, then gate with fused silu(gate)*up
    run_w<0, __half>(p_n2h, p_wup, p_uph, nullptr, TSEQ, FFNN, CEMB, FFNN);
    run_w<4, __half>(p_n2h, p_wgate, p_acth, p_uph, TSEQ, FFNN, CEMB, FFNN);
    // 12. out = act @ down_w^T + x2
    run_w<1, float>(p_acth, p_wdown, out, p_x2, TSEQ, CEMB, FFNN, CEMB);
}

// round 15
// speedup vs baseline: 1.3344x; 1.1361x over previous
#include <cuda_runtime.h>
#include <cuda_fp16.h>
#include <mma.h>
#include <cstdint>

using namespace nvcuda;

#define TSEQ 2048
#define CEMB 4096
#define QKVN 6144
#define FFNN 11008
#define NHEAD 32
#define NGRP 8
#define HSZ 128

// ------------------------- scratch (device globals) -------------------------
__device__ float g_qkv[TSEQ * QKVN];
__device__ float g_scaling[TSEQ * CEMB];
__device__ float g_scale_t[NHEAD * TSEQ];
__device__ float g_x2[TSEQ * CEMB];
__device__ __half g_n1h[TSEQ * CEMB];
__device__ __half g_n2h[TSEQ * CEMB];
__device__ __half g_qh[NHEAD * TSEQ * HSZ];
__device__ __half g_kh[NGRP * TSEQ * HSZ];
__device__ __half g_vh[NGRP * TSEQ * HSZ];
__device__ __half g_yh[TSEQ * CEMB];
__device__ __half g_uph[TSEQ * FFNN];
__device__ __half g_acth[TSEQ * FFNN];
__device__ __half g_wqkv[QKVN * CEMB];
__device__ __half g_wscale[CEMB * CEMB];
__device__ __half g_wproj[CEMB * CEMB];
__device__ __half g_wgate[FFNN * CEMB];
__device__ __half g_wup[FFNN * CEMB];
__device__ __half g_wdown[CEMB * FFNN];

// ------------------------- low-level helpers -------------------------
__device__ __forceinline__ void cp_async16h(__half* smem, const __half* gmem)
{
    uint32_t s = (uint32_t)__cvta_generic_to_shared(smem);
    asm volatile("cp.async.cg.shared.global [%0], [%1], 16;\n" :: "r"(s), "l"(gmem));
}
#define CP_COMMIT asm volatile("cp.async.commit_group;\n" ::: "memory")

__device__ __forceinline__ void ldsm4(uint32_t* r, uint32_t addr)
{
    asm volatile("ldmatrix.sync.aligned.m8n8.x4.shared.b16 {%0,%1,%2,%3}, [%4];"
                 : "=r"(r[0]), "=r"(r[1]), "=r"(r[2]), "=r"(r[3]) : "r"(addr));
}
__device__ __forceinline__ void ldsm4t(uint32_t* r, uint32_t addr)
{
    asm volatile("ldmatrix.sync.aligned.m8n8.x4.trans.shared.b16 {%0,%1,%2,%3}, [%4];"
                 : "=r"(r[0]), "=r"(r[1]), "=r"(r[2]), "=r"(r[3]) : "r"(addr));
}
__device__ __forceinline__ void mma16816(float* c, const uint32_t* a, const uint32_t* b)
{
    asm volatile(
        "mma.sync.aligned.m16n8k16.row.col.f32.f16.f16.f32 "
        "{%0,%1,%2,%3}, {%4,%5,%6,%7}, {%8,%9}, {%0,%1,%2,%3};"
        : "+f"(c[0]), "+f"(c[1]), "+f"(c[2]), "+f"(c[3])
        : "r"(a[0]), "r"(a[1]), "r"(a[2]), "r"(a[3]), "r"(b[0]), "r"(b[1]));
}
__device__ __forceinline__ uint32_t pack_h2(float a, float b)
{
    __half2 h = __floats2half2_rn(a, b);
    return *(uint32_t*)&h;
}

// ===================== flash attention ===============================
// One CTA = (head, 128-query tile). 8 warps x 16 q rows. Online softmax.
// Q is pre-scaled by sf*scale_t. Output y[t][head*128+d] fp16, /= rowsum.
#define FLDT 136
#define FSMEM (5 * 128 * FLDT * 2)   // Q + 2xK + 2xV tiles = 174080 B

__global__ void __launch_bounds__(256, 1) flash_kernel(
    const __half* __restrict__ Qg_, const __half* __restrict__ Kg_,
    const __half* __restrict__ Vg_, __half* __restrict__ Y)
{
    extern __shared__ __align__(16) __half smf[];
    const int tid = threadIdx.x;
    const int lane = tid & 31, warp = tid >> 5;
    const int head = blockIdx.y, grp = head >> 2;
    const int q0 = blockIdx.x * 128;

    const __half* Qg = Qg_ + ((size_t)head * TSEQ + q0) * HSZ;
    const __half* Kg = Kg_ + (size_t)grp * TSEQ * HSZ;
    const __half* Vg = Vg_ + (size_t)grp * TSEQ * HSZ;

    __half* Qs = smf;
    __half* Ksb[2] = { smf + 128 * FLDT, smf + 2 * 128 * FLDT };
    __half* Vsb[2] = { smf + 3 * 128 * FLDT, smf + 4 * 128 * FLDT };

    const int lr = tid >> 4;            // 0..15
    const int lc = (tid & 15) << 3;     // 0..120 step 8

    // async loads: Q tile + K0/V0
#pragma unroll
    for (int i = 0; i < 8; i++) {
        int r = lr + 16 * i;
        cp_async16h(Qs + r * FLDT + lc, Qg + (size_t)r * HSZ + lc);
    }
#pragma unroll
    for (int i = 0; i < 8; i++) {
        int r = lr + 16 * i;
        cp_async16h(Ksb[0] + r * FLDT + lc, Kg + (size_t)r * HSZ + lc);
        cp_async16h(Vsb[0] + r * FLDT + lc, Vg + (size_t)r * HSZ + lc);
    }
    CP_COMMIT;

    const uint32_t sb = (uint32_t)__cvta_generic_to_shared(smf);

    // lane patterns (documented m16n8k16 fragment layouts)
    const int rA = (lane & 7) + ((lane >> 3) & 1) * 8;  // A / trans-B row
    const int cA = (lane >> 4) * 8;
    const int rB = (lane & 7) + (lane >> 4) * 8;        // non-trans B row
    const int cB = ((lane >> 3) & 1) * 8;

    asm volatile("cp.async.wait_group 0;\n" ::: "memory");
    __syncthreads();

    // Q fragments: 8 k-steps of d, register-resident for whole kernel
    uint32_t qa[8][4];
#pragma unroll
    for (int ks = 0; ks < 8; ks++)
        ldsm4(qa[ks], sb + ((warp * 16 + rA) * FLDT + ks * 16 + cA) * 2);

    float oacc[16][4];
#pragma unroll
    for (int i = 0; i < 16; i++) { oacc[i][0]=0.f; oacc[i][1]=0.f; oacc[i][2]=0.f; oacc[i][3]=0.f; }
    float rm0 = -1e30f, rm1 = -1e30f, ls0 = 0.f, ls1 = 0.f;

    for (int kt = 0; kt < 16; kt++) {
        const int b = kt & 1;
        if (kt < 15) {
            const __half* Kn = Kg + (size_t)(kt + 1) * 128 * HSZ;
            const __half* Vn = Vg + (size_t)(kt + 1) * 128 * HSZ;
            __half* Kd = Ksb[b ^ 1];
            __half* Vd = Vsb[b ^ 1];
#pragma unroll
            for (int i = 0; i < 8; i++) {
                int r = lr + 16 * i;
                cp_async16h(Kd + r * FLDT + lc, Kn + (size_t)r * HSZ + lc);
                cp_async16h(Vd + r * FLDT + lc, Vn + (size_t)r * HSZ + lc);
            }
            CP_COMMIT;
        }

        const uint32_t Kb = sb + (1 + b) * 128 * FLDT * 2;
        const uint32_t Vb = sb + (3 + b) * 128 * FLDT * 2;

        // ---- S = Q K^T  (16 q x 128 kv per warp) ----
        float sacc[16][4];
#pragma unroll
        for (int i = 0; i < 16; i++) { sacc[i][0]=0.f; sacc[i][1]=0.f; sacc[i][2]=0.f; sacc[i][3]=0.f; }
#pragma unroll
        for (int np = 0; np < 8; np++) {
#pragma unroll
            for (int k = 0; k < 8; k++) {
                uint32_t kb[4];
                ldsm4(kb, Kb + ((np * 16 + rB) * FLDT + k * 16 + cB) * 2);
                mma16816(sacc[2 * np],     qa[k], kb);
                mma16816(sacc[2 * np + 1], qa[k], kb + 2);
            }
        }

        // ---- online softmax (rows lane/4 and lane/4+8) ----
        float tm0 = -1e30f, tm1 = -1e30f;
#pragma unroll
        for (int i = 0; i < 16; i++) {
            tm0 = fmaxf(tm0, fmaxf(sacc[i][0], sacc[i][1]));
            tm1 = fmaxf(tm1, fmaxf(sacc[i][2], sacc[i][3]));
        }
        tm0 = fmaxf(tm0, __shfl_xor_sync(0xffffffffu, tm0, 1));
        tm0 = fmaxf(tm0, __shfl_xor_sync(0xffffffffu, tm0, 2));
        tm1 = fmaxf(tm1, __shfl_xor_sync(0xffffffffu, tm1, 1));
        tm1 = fmaxf(tm1, __shfl_xor_sync(0xffffffffu, tm1, 2));
        const float nm0 = fmaxf(rm0, tm0), nm1 = fmaxf(rm1, tm1);
        const float al0 = __expf(rm0 - nm0), al1 = __expf(rm1 - nm1);
        rm0 = nm0; rm1 = nm1;

        float s0 = 0.f, s1 = 0.f;
#pragma unroll
        for (int i = 0; i < 16; i++) {
            sacc[i][0] = __expf(sacc[i][0] - nm0);
            sacc[i][1] = __expf(sacc[i][1] - nm0);
            sacc[i][2] = __expf(sacc[i][2] - nm1);
            sacc[i][3] = __expf(sacc[i][3] - nm1);
            s0 += sacc[i][0] + sacc[i][1];
            s1 += sacc[i][2] + sacc[i][3];
        }
        s0 += __shfl_xor_sync(0xffffffffu, s0, 1);
        s0 += __shfl_xor_sync(0xffffffffu, s0, 2);
        s1 += __shfl_xor_sync(0xffffffffu, s1, 1);
        s1 += __shfl_xor_sync(0xffffffffu, s1, 2);
        ls0 = ls0 * al0 + s0;
        ls1 = ls1 * al1 + s1;

#pragma unroll
        for (int i = 0; i < 16; i++) {
            oacc[i][0] *= al0; oacc[i][1] *= al0;
            oacc[i][2] *= al1; oacc[i][3] *= al1;
        }

        // ---- pack P (C-frag -> A-frag is pure register repack) ----
        uint32_t pa[8][4];
#pragma unroll
        for (int k = 0; k < 8; k++) {
            pa[k][0] = pack_h2(sacc[2 * k][0],     sacc[2 * k][1]);
            pa[k][1] = pack_h2(sacc[2 * k][2],     sacc[2 * k][3]);
            pa[k][2] = pack_h2(sacc[2 * k + 1][0], sacc[2 * k + 1][1]);
            pa[k][3] = pack_h2(sacc[2 * k + 1][2], sacc[2 * k + 1][3]);
        }

        // ---- O += P V ----
#pragma unroll
        for (int k = 0; k < 8; k++) {
#pragma unroll
            for (int nd = 0; nd < 8; nd++) {
                uint32_t vb[4];
                ldsm4t(vb, Vb + ((k * 16 + rA) * FLDT + nd * 16 + cA) * 2);
                mma16816(oacc[2 * nd],     pa[k], vb);
                mma16816(oacc[2 * nd + 1], pa[k], vb + 2);
            }
        }

        if (kt < 15) asm volatile("cp.async.wait_group 0;\n" ::: "memory");
        __syncthreads();
    }

    // ---- epilogue: y = O / rowsum, fp16, [t][head*128+d] ----
    const float il0 = 1.f / ls0, il1 = 1.f / ls1;
    const int r0g = q0 + warp * 16 + (lane >> 2);
    __half* Yp = Y + (size_t)r0g * CEMB + head * 128 + 2 * (lane & 3);
#pragma unroll
    for (int nt = 0; nt < 16; nt++) {
        __half2 v0 = __floats2half2_rn(oacc[nt][0] * il0, oacc[nt][1] * il0);
        __half2 v1 = __floats2half2_rn(oacc[nt][2] * il1, oacc[nt][3] * il1);
        *(__half2*)(Yp + nt * 8) = v0;
        *(__half2*)(Yp + (size_t)8 * CEMB + nt * 8) = v1;
    }
}

// ===================== wgemm: weight GEMMs (R13 winner) ======================
#define WLD 40
#define WSTG_H 10240
#define WSMEM 61440

template <int EPI, typename TO>
__global__ void __launch_bounds__(128, 2) wgemm(
    const __half* __restrict__ A, const __half* __restrict__ B, TO* __restrict__ C,
    const void* __restrict__ ep, int M, int N, int K, int ldc)
{
    extern __shared__ __align__(16) char smraw[];
    __half* smh = (__half*)smraw;

    const int m0 = blockIdx.y * 128;
    const int n0 = blockIdx.x * 128;
    const int tid = threadIdx.x;
    const int lane = tid & 31;
    const int warp = tid >> 5;
    const int wr = warp >> 1;
    const int wc = warp & 1;

    const int lr = tid >> 2;
    const int lc = (tid & 3) << 3;

    wmma::fragment<wmma::accumulator, 16, 16, 16, float> acc[4][4];
#pragma unroll
    for (int i = 0; i < 4; i++)
#pragma unroll
        for (int j = 0; j < 4; j++) wmma::fill_fragment(acc[i][j], 0.0f);

    const int KT = K >> 5;

    auto load_tile = [&](int kt, int st) {
        __half* As = smh + st * WSTG_H;
        __half* Bs = As + 128 * WLD;
        const int k0 = kt << 5;
#pragma unroll
        for (int it = 0; it < 4; it++) {
            int r = lr + it * 32;
            cp_async16h(As + r * WLD + lc, A + (long long)(m0 + r) * K + k0 + lc);
            cp_async16h(Bs + r * WLD + lc, B + (long long)(n0 + r) * K + k0 + lc);
        }
    };

    load_tile(0, 0); CP_COMMIT;
    load_tile(1, 1); CP_COMMIT;

    for (int kt = 0; kt < KT; kt++) {
        asm volatile("cp.async.wait_group 1;\n" ::: "memory");
        __syncthreads();
        if (kt + 2 < KT) load_tile(kt + 2, (kt + 2) % 3);
        CP_COMMIT;

        __half* As = smh + (kt % 3) * WSTG_H;
        __half* Bs = As + 128 * WLD;
#pragma unroll
        for (int kk = 0; kk < 2; kk++) {
            wmma::fragment<wmma::matrix_a, 16, 16, 16, __half, wmma::row_major> fa[4];
#pragma unroll
            for (int i = 0; i < 4; i++)
                wmma::load_matrix_sync(fa[i], As + (wr * 64 + i * 16) * WLD + kk * 16, WLD);
#pragma unroll
            for (int j = 0; j < 4; j++) {
                wmma::fragment<wmma::matrix_b, 16, 16, 16, __half, wmma::col_major> fb;
                wmma::load_matrix_sync(fb, Bs + (wc * 64 + j * 16) * WLD + kk * 16, WLD);
#pragma unroll
                for (int i = 0; i < 4; i++)
                    wmma::mma_sync(acc[i][j], fa[i], fb, acc[i][j]);
            }
        }
    }
    __syncthreads();

    float* stg = (float*)smraw + warp * (64 * 36);
    const float* epf = (const float*)ep;
    const __half* eph = (const __half*)ep;
#pragma unroll
    for (int h = 0; h < 2; h++) {
#pragma unroll
        for (int i = 0; i < 4; i++)
#pragma unroll
            for (int j = 0; j < 2; j++)
                wmma::store_matrix_sync(stg + (i * 16) * 36 + j * 16, acc[i][2 * h + j], 36,
                                        wmma::mem_row_major);
        __syncwarp();
        const int gn = n0 + wc * 64 + h * 32 + lane;
#pragma unroll 4
        for (int r = 0; r < 64; r++) {
            const int gm = m0 + wr * 64 + r;
            float v = stg[r * 36 + lane];
            if (EPI == 1) v += epf[(long long)gm * ldc + gn];
            if (EPI == 2) v = fmaxf(v + epf[gn], 0.0f);
            if (EPI == 4) v = (v / (1.f + __expf(-v))) * __half2float(eph[(long long)gm * ldc + gn]);
            if (sizeof(TO) == 2)
                ((__half*)C)[(long long)gm * ldc + gn] = __float2half(v);
            else
                ((float*)C)[(long long)gm * ldc + gn] = v;
        }
        __syncwarp();
    }
}

// ------------------------- small kernels -------------------------

__global__ void w2h_kernel(const float* __restrict__ in, __half* __restrict__ out)
{
    const long long i = ((long long)blockIdx.x * 256 + threadIdx.x) * 4;
    float4 v = *(const float4*)(in + i);
    __half2* o = (__half2*)(out + i);
    o[0] = __floats2half2_rn(v.x, v.y);
    o[1] = __floats2half2_rn(v.z, v.w);
}

__global__ void rmsnorm_kernel(const float* __restrict__ x, const float* __restrict__ w,
                               __half* __restrict__ out)
{
    __shared__ float red[256];
    const int t = blockIdx.x;
    const float* row = x + (size_t)t * CEMB;
    __half* orow = out + (size_t)t * CEMB;
    const int tid = threadIdx.x;
    float s = 0.f;
    for (int i = tid; i < CEMB; i += 256) { float v = row[i]; s += v * v; }
    red[tid] = s;
    __syncthreads();
    for (int st = 128; st > 0; st >>= 1) {
        if (tid < st) red[tid] += red[tid + st];
        __syncthreads();
    }
    const float inv = rsqrtf(red[0] * (1.0f / CEMB) + 1e-5f);
    for (int i = tid; i < CEMB; i += 256) orow[i] = __float2half(row[i] * inv * w[i]);
}

__global__ void scale_reduce_kernel(const float* __restrict__ s, float* __restrict__ st)
{
    const int pair = blockIdx.x * 8 + (threadIdx.x >> 5);
    const int lane = threadIdx.x & 31;
    const int t = pair >> 5;
    const int h = pair & 31;
    const float* p = s + (size_t)t * CEMB + h * HSZ;
    float acc = 0.f;
    for (int d = lane; d < HSZ; d += 32) acc += p[d];
    for (int o = 16; o; o >>= 1) acc += __shfl_down_sync(0xffffffffu, acc, o);
    if (lane == 0) st[h * TSEQ + t] = acc * (1.0f / HSZ);
}

__global__ void qkv_rope_kernel(const float* __restrict__ qkv, const float* __restrict__ cs,
                                const float* __restrict__ sn, const float* __restrict__ st,
                                __half* __restrict__ q, __half* __restrict__ k,
                                __half* __restrict__ v)
{
    const int idx = blockIdx.x * 256 + threadIdx.x;
    const int d = idx & 127;
    const int rest = idx >> 7;
    const int slot = rest % 48;
    const int t = rest / 48;
    const int g = slot / 6;
    const int i = slot % 6;
    const float* src = qkv + (size_t)t * QKVN + g * 768 + i * 128;
    const float x0 = src[d];
    if (i == 5) {
        v[((size_t)g * TSEQ + t) * HSZ + d] = __float2half(x0);
        return;
    }
    const float xp = src[d ^ 64];
    const float rot = (d < 64) ? -xp : xp;
    const float val = x0 * cs[t * 128 + d] + rot * sn[t * 128 + d];
    if (i == 4) {
        k[((size_t)g * TSEQ + t) * HSZ + d] = __float2half(val);
    } else {
        const int h = g * 4 + i;
        q[((size_t)h * TSEQ + t) * HSZ + d] =
            __float2half(val * (0.08838834764831845f * st[h * TSEQ + t]));
    }
}

// ------------------------- host side -------------------------

template <int EPI, typename TO>
static inline void run_w(const __half* A, const __half* B, TO* C, const void* ep,
                         int M, int N, int K, int ldc)
{
    cudaFuncSetAttribute(wgemm<EPI, TO>,
                         cudaFuncAttributeMaxDynamicSharedMemorySize, WSMEM);
    dim3 grid(N / 128, M / 128);
    wgemm<EPI, TO><<<grid, 128, WSMEM>>>(A, B, C, ep, M, N, K, ldc);
}

static inline void conv_w(const float* in, __half* out, long long n)
{
    w2h_kernel<<<(unsigned)(n / 1024), 256>>>(in, out);
}

extern "C" void kernel_launch(void* const* d_in, const int* in_sizes, int n_in,
                              void* d_out, int out_size)
{
    (void)in_sizes; (void)n_in; (void)out_size;
    const float* x       = (const float*)d_in[0];
    const float* cosp    = (const float*)d_in[1];
    const float* sinp    = (const float*)d_in[2];
    const float* n1w     = (const float*)d_in[3];
    const float* n2w     = (const float*)d_in[4];
    const float* attn_w  = (const float*)d_in[5];
    const float* proj_w  = (const float*)d_in[6];
    const float* scale_w = (const float*)d_in[7];
    const float* scale_b = (const float*)d_in[8];
    const float* gate_w  = (const float*)d_in[9];
    const float* up_w    = (const float*)d_in[10];
    const float* down_w  = (const float*)d_in[11];
    float* out = (float*)d_out;

    float *p_qkv, *p_scaling, *p_st, *p_x2;
    __half *p_n1h, *p_n2h, *p_qh, *p_kh, *p_vh, *p_yh, *p_uph, *p_acth;
    __half *p_wqkv, *p_wscale, *p_wproj, *p_wgate, *p_wup, *p_wdown;
    cudaGetSymbolAddress((void**)&p_qkv, g_qkv);
    cudaGetSymbolAddress((void**)&p_scaling, g_scaling);
    cudaGetSymbolAddress((void**)&p_st, g_scale_t);
    cudaGetSymbolAddress((void**)&p_x2, g_x2);
    cudaGetSymbolAddress((void**)&p_n1h, g_n1h);
    cudaGetSymbolAddress((void**)&p_n2h, g_n2h);
    cudaGetSymbolAddress((void**)&p_qh, g_qh);
    cudaGetSymbolAddress((void**)&p_kh, g_kh);
    cudaGetSymbolAddress((void**)&p_vh, g_vh);
    cudaGetSymbolAddress((void**)&p_yh, g_yh);
    cudaGetSymbolAddress((void**)&p_uph, g_uph);
    cudaGetSymbolAddress((void**)&p_acth, g_acth);
    cudaGetSymbolAddress((void**)&p_wqkv, g_wqkv);
    cudaGetSymbolAddress((void**)&p_wscale, g_wscale);
    cudaGetSymbolAddress((void**)&p_wproj, g_wproj);
    cudaGetSymbolAddress((void**)&p_wgate, g_wgate);
    cudaGetSymbolAddress((void**)&p_wup, g_wup);
    cudaGetSymbolAddress((void**)&p_wdown, g_wdown);

    // 0. weights -> fp16
    conv_w(attn_w,  p_wqkv,   (long long)QKVN * CEMB);
    conv_w(scale_w, p_wscale, (long long)CEMB * CEMB);
    conv_w(proj_w,  p_wproj,  (long long)CEMB * CEMB);
    conv_w(gate_w,  p_wgate,  (long long)FFNN * CEMB);
    conv_w(up_w,    p_wup,    (long long)FFNN * CEMB);
    conv_w(down_w,  p_wdown,  (long long)CEMB * FFNN);

    // 1. n1 = rmsnorm(x)
    rmsnorm_kernel<<<TSEQ, 256>>>(x, n1w, p_n1h);
    // 2. qkv = n1 @ attn_w^T
    run_w<0, float>(p_n1h, p_wqkv, p_qkv, nullptr, TSEQ, QKVN, CEMB, QKVN);
    // 3. scaling = relu(n1 @ scale_w^T + b)
    run_w<2, float>(p_n1h, p_wscale, p_scaling, scale_b, TSEQ, CEMB, CEMB, CEMB);
    // 4. scale_t
    scale_reduce_kernel<<<TSEQ * NHEAD / 8, 256>>>(p_scaling, p_st);
    // 5. split + rope (fold sf*scale_t into q)
    qkv_rope_kernel<<<TSEQ * 48 * HSZ / 256, 256>>>(p_qkv, cosp, sinp, p_st, p_qh, p_kh, p_vh);
    // 6-8. fused flash attention -> y fp16
    cudaFuncSetAttribute(flash_kernel, cudaFuncAttributeMaxDynamicSharedMemorySize, FSMEM);
    {
        dim3 fg(TSEQ / 128, NHEAD);
        flash_kernel<<<fg, 256, FSMEM>>>(p_qh, p_kh, p_vh, p_yh);
    }
    // 9. x2 = y @ proj_w^T + x
    run_w<1, float>(p_yh, p_wproj, p_x2, x, TSEQ, CEMB, CEMB, CEMB);
    // 10. n2 = rmsnorm(x2)
    rmsnorm_kernel<<<TSEQ, 256>>>(p_x2, n2w, p_n2h);
    // 11. up, then gate with fused silu(gate)*up
    run_w<0, __half>(p_n2h, p_wup, p_uph, nullptr, TSEQ, FFNN, CEMB, FFNN);
    run_w<4, __half>(p_n2h, p_wgate, p_acth, p_uph, TSEQ, FFNN, CEMB, FFNN);
    // 12. out = act @ down_w^T + x2
    run_w<1, float>(p_acth, p_wdown, out, p_x2, TSEQ, CEMB, FFNN, CEMB);
}